// round 15
// baseline (speedup 1.0000x reference)
#include <cuda_runtime.h>
#include <cuda_bf16.h>
#include <math.h>
#include <stdint.h>

// Problem constants
#define NB 4096
#define ND 1024
#define NC 1000
#define NP 8
#define NCP 8000
#define LEN_KEEP 870
#define N_MASKED 154
#define INV_TEMP 10.0f
#define MARGIN 0.3f

// ================= scratch (device globals) =================================
__device__ __nv_bfloat16 g_fA[NB * ND];     // normalized features (bf16)
__device__ __nv_bfloat16 g_pB[NCP * ND];    // normalized proxies (bf16)
__device__ __nv_bfloat16 g_mA[NB * ND];     // masked features (bf16)
__device__ __nv_bfloat16 g_cA[NB * ND];     // attention-combined (bf16)
__device__ __nv_bfloat16 g_ewb[ND * ND];    // enc_w bf16
__device__ __nv_bfloat16 g_dwb[ND * ND];    // dec_w bf16
__device__ float g_cs[NB * NC];
__device__ float g_maskf[NB * ND];
__device__ float g_y1[NB * ND];
__device__ float g_y2[NB * ND];
__device__ float g_acc[2];

__device__ __forceinline__ uint32_t smem_u32(const void* p) {
    uint32_t a;
    asm("{ .reg .u64 t; cvta.to.shared.u64 t, %1; cvt.u32.u64 %0, t; }" : "=r"(a) : "l"(p));
    return a;
}

// ================= block reductions (blockDim == 256) =======================
__device__ __forceinline__ float block_reduce_sum(float v) {
    __shared__ float s_red[8];
    int tid = threadIdx.x;
    #pragma unroll
    for (int o = 16; o; o >>= 1) v += __shfl_xor_sync(0xffffffffu, v, o);
    __syncthreads();
    if ((tid & 31) == 0) s_red[tid >> 5] = v;
    __syncthreads();
    if (tid < 32) {
        float x = (tid < 8) ? s_red[tid] : 0.0f;
        #pragma unroll
        for (int o = 4; o; o >>= 1) x += __shfl_xor_sync(0xffffffffu, x, o);
        if (tid == 0) s_red[0] = x;
    }
    __syncthreads();
    float r = s_red[0];
    __syncthreads();
    return r;
}
__device__ __forceinline__ float block_reduce_max(float v) {
    __shared__ float s_red[8];
    int tid = threadIdx.x;
    #pragma unroll
    for (int o = 16; o; o >>= 1) v = fmaxf(v, __shfl_xor_sync(0xffffffffu, v, o));
    __syncthreads();
    if ((tid & 31) == 0) s_red[tid >> 5] = v;
    __syncthreads();
    if (tid < 32) {
        float x = (tid < 8) ? s_red[tid] : -3.4e38f;
        #pragma unroll
        for (int o = 4; o; o >>= 1) x = fmaxf(x, __shfl_xor_sync(0xffffffffu, x, o));
        if (tid == 0) s_red[0] = x;
    }
    __syncthreads();
    float r = s_red[0];
    __syncthreads();
    return r;
}

// ================= fused: init + feat normalize + mask ======================
__global__ void __launch_bounds__(256) k_featmask(const float* __restrict__ features,
                                                  const float* __restrict__ noise) {
    int row = blockIdx.x, tid = threadIdx.x;
    if (row == 0 && tid == 0) { g_acc[0] = 0.0f; g_acc[1] = 0.0f; }
    const float* s = features + (size_t)row * ND;
    float v[4], ss = 0.0f;
    #pragma unroll
    for (int r = 0; r < 4; r++) { v[r] = s[tid + r * 256]; ss += v[r] * v[r]; }
    ss = block_reduce_sum(ss);
    float scale = 1.0f / fmaxf(sqrtf(ss), 1e-12f);
    #pragma unroll
    for (int r = 0; r < 4; r++)
        g_fA[(size_t)row * ND + tid + r * 256] = __float2bfloat16_rn(v[r] * scale);

    // radix select on noise bits (positive floats: bit order == value order)
    __shared__ unsigned sh[ND];
    __shared__ int hist[256];
    __shared__ int sel_digit, sel_rem, s_cl;
    const unsigned* nrow = (const unsigned*)noise + (size_t)row * ND;
    for (int i = tid; i < ND; i += 256) sh[i] = nrow[i];
    __syncthreads();

    unsigned prefix = 0;
    int remaining = LEN_KEEP - 1;
    for (int shift = 24; shift >= 0; shift -= 8) {
        hist[tid] = 0;
        __syncthreads();
        unsigned pmask = (shift == 24) ? 0u : (0xFFFFFFFFu << (shift + 8));
        for (int i = tid; i < ND; i += 256) {
            unsigned w = sh[i];
            if ((w & pmask) == prefix) atomicAdd(&hist[(w >> shift) & 0xFF], 1);
        }
        __syncthreads();
        if (tid == 0) {
            int cum = 0, d = 0;
            for (; d < 256; d++) {
                int h = hist[d];
                if (cum + h > remaining) break;
                cum += h;
            }
            sel_digit = d; sel_rem = remaining - cum;
        }
        __syncthreads();
        prefix |= ((unsigned)sel_digit) << shift;
        remaining = sel_rem;
        __syncthreads();
    }
    unsigned T = prefix;

    if (tid == 0) s_cl = 0;
    __syncthreads();
    int local = 0;
    for (int i = tid; i < ND; i += 256) if (sh[i] < T) local++;
    atomicAdd(&s_cl, local);
    __syncthreads();
    int quota = LEN_KEEP - s_cl;

    #pragma unroll
    for (int r = 0; r < 4; r++) {
        int i = tid + r * 256;
        unsigned w = sh[i];
        float m;
        if (w < T) m = 1.0f;
        else if (w > T) m = 0.0f;
        else {
            int rk = 0;
            for (int j = 0; j < i; j++) rk += (sh[j] == T) ? 1 : 0;
            m = (rk < quota) ? 1.0f : 0.0f;
        }
        size_t idx = (size_t)row * ND + i;
        g_maskf[idx] = m;
        g_mA[idx] = __float2bfloat16_rn(v[r] * m);
    }
}

__global__ void __launch_bounds__(256) k_norm_prox(const float* __restrict__ src) {
    int row = blockIdx.x, tid = threadIdx.x;
    const float* s = src + (size_t)row * ND;
    float v[4], ss = 0.0f;
    #pragma unroll
    for (int r = 0; r < 4; r++) { v[r] = s[tid + r * 256]; ss += v[r] * v[r]; }
    ss = block_reduce_sum(ss);
    float scale = 1.0f / fmaxf(sqrtf(ss), 1e-12f);
    #pragma unroll
    for (int r = 0; r < 4; r++) {
        size_t i = (size_t)row * ND + tid + r * 256;
        g_pB[i] = __float2bfloat16_rn(v[r] * scale);
    }
}

__global__ void __launch_bounds__(256) k_conv_w(const float* __restrict__ ew,
                                                const float* __restrict__ dw) {
    int i0 = (blockIdx.x * 256 + threadIdx.x) * 4;
    if (i0 < ND * ND) {
        float4 e4 = *(const float4*)(ew + i0);
        float4 d4 = *(const float4*)(dw + i0);
        __nv_bfloat162 e01 = {__float2bfloat16_rn(e4.x), __float2bfloat16_rn(e4.y)};
        __nv_bfloat162 e23 = {__float2bfloat16_rn(e4.z), __float2bfloat16_rn(e4.w)};
        __nv_bfloat162 d01 = {__float2bfloat16_rn(d4.x), __float2bfloat16_rn(d4.y)};
        __nv_bfloat162 d23 = {__float2bfloat16_rn(d4.z), __float2bfloat16_rn(d4.w)};
        *(__nv_bfloat162*)(g_ewb + i0) = e01;
        *(__nv_bfloat162*)(g_ewb + i0 + 2) = e23;
        *(__nv_bfloat162*)(g_dwb + i0) = d01;
        *(__nv_bfloat162*)(g_dwb + i0 + 2) = d23;
    }
}

// ================= HMMA bf16 GEMM: C[M,N] = A[M,K] * B[N,K]^T ===============
// 128x128 block tile, BK=64, 256 thr (8 warps 2x4), warp 64x32 = 4x4 m16n8k16
// 2-stage cp.async double buffer, single leading barrier per chunk.
#define RSTRIDE_B 144                 // bytes per SMEM row (64 bf16 + 8 pad)
#define TILE_BYTES (128 * RSTRIDE_B)  // 18432
#define STAGE_BYTES (2 * TILE_BYTES)  // A+B = 36864
#define SMEM_GEMM (2 * STAGE_BYTES)   // 73728

template <int MODE>
__global__ void __launch_bounds__(256, 2) k_gemm(int mrow0) {
    extern __shared__ __align__(16) char smem[];
    const __nv_bfloat16* A = (MODE == 0) ? g_fA : (MODE == 1) ? g_mA : g_cA;
    const __nv_bfloat16* B = (MODE == 0) ? g_pB : (MODE == 1) ? g_ewb : g_dwb;
    const int nrowsB = (MODE == 0) ? NCP : ND;

    int tid = threadIdx.x, lane = tid & 31, wid = tid >> 5;
    int wr = wid & 1, wc = wid >> 1;
    int m0 = mrow0 + blockIdx.y * 128, n0 = blockIdx.x * 128;
    uint32_t sb = smem_u32(smem);

    int aRow = (lane & 7) | (((lane >> 3) & 1) << 3);
    uint32_t aOffBase = (uint32_t)((wr * 64 + aRow) * RSTRIDE_B + (lane >> 4) * 16);
    int bRow = (lane & 7) + ((lane >> 4) << 3);
    uint32_t bOffBase = (uint32_t)((wc * 32 + bRow) * RSTRIDE_B + ((lane >> 3) & 1) * 16);

    float acc[4][4][4];
    #pragma unroll
    for (int i = 0; i < 4; i++)
        #pragma unroll
        for (int j = 0; j < 4; j++)
            #pragma unroll
            for (int q = 0; q < 4; q++) acc[i][j][q] = 0.0f;

    const int NCHUNK = ND / 64;   // 16

    auto load_chunk = [&](int c, int buf) {
        int kb = c * 64;
        uint32_t a_s = sb + (uint32_t)(buf * STAGE_BYTES);
        uint32_t b_s = a_s + TILE_BYTES;
        #pragma unroll
        for (int j = 0; j < 4; j++) {
            int u = tid + j * 256;
            int row = u >> 3, seg = u & 7;
            uint32_t sa = a_s + row * RSTRIDE_B + seg * 16;
            const void* ga = A + (size_t)(m0 + row) * ND + kb + seg * 8;
            asm volatile("cp.async.cg.shared.global [%0], [%1], 16;" :: "r"(sa), "l"(ga));
        }
        #pragma unroll
        for (int j = 0; j < 4; j++) {
            int u = tid + j * 256;
            int row = u >> 3, seg = u & 7;
            int grow = n0 + row;
            uint32_t sbb = b_s + row * RSTRIDE_B + seg * 16;
            const void* gb = B + (size_t)(grow < nrowsB ? grow : 0) * ND + kb + seg * 8;
            int srcsz = (grow < nrowsB) ? 16 : 0;
            asm volatile("cp.async.cg.shared.global [%0], [%1], 16, %2;" :: "r"(sbb), "l"(gb), "r"(srcsz));
        }
        asm volatile("cp.async.commit_group;" ::: "memory");
    };

    load_chunk(0, 0);
    for (int c = 0; c < NCHUNK; c++) {
        asm volatile("cp.async.wait_group 0;" ::: "memory");
        __syncthreads();
        if (c + 1 < NCHUNK) load_chunk(c + 1, (c + 1) & 1);
        uint32_t a_s = sb + (uint32_t)((c & 1) * STAGE_BYTES);
        uint32_t b_s = a_s + TILE_BYTES;
        #pragma unroll
        for (int kk = 0; kk < 4; kk++) {
            uint32_t afr[4][4], bfr[4][2];
            #pragma unroll
            for (int mt = 0; mt < 4; mt++) {
                uint32_t ad = a_s + aOffBase + mt * 16 * RSTRIDE_B + kk * 32;
                asm volatile("ldmatrix.sync.aligned.m8n8.x4.shared.b16 {%0,%1,%2,%3}, [%4];"
                             : "=r"(afr[mt][0]), "=r"(afr[mt][1]), "=r"(afr[mt][2]), "=r"(afr[mt][3])
                             : "r"(ad));
            }
            #pragma unroll
            for (int ntp = 0; ntp < 2; ntp++) {
                uint32_t bd = b_s + bOffBase + ntp * 16 * RSTRIDE_B + kk * 32;
                asm volatile("ldmatrix.sync.aligned.m8n8.x4.shared.b16 {%0,%1,%2,%3}, [%4];"
                             : "=r"(bfr[2 * ntp][0]), "=r"(bfr[2 * ntp][1]),
                               "=r"(bfr[2 * ntp + 1][0]), "=r"(bfr[2 * ntp + 1][1])
                             : "r"(bd));
            }
            #pragma unroll
            for (int mt = 0; mt < 4; mt++)
                #pragma unroll
                for (int nt = 0; nt < 4; nt++)
                    asm volatile("mma.sync.aligned.m16n8k16.row.col.f32.bf16.bf16.f32 "
                                 "{%0,%1,%2,%3}, {%4,%5,%6,%7}, {%8,%9}, {%0,%1,%2,%3};"
                                 : "+f"(acc[mt][nt][0]), "+f"(acc[mt][nt][1]),
                                   "+f"(acc[mt][nt][2]), "+f"(acc[mt][nt][3])
                                 : "r"(afr[mt][0]), "r"(afr[mt][1]), "r"(afr[mt][2]), "r"(afr[mt][3]),
                                   "r"(bfr[nt][0]), "r"(bfr[nt][1]));
        }
    }

    int qr = lane >> 2, qc = lane & 3;
    if (MODE == 0) {
        #pragma unroll
        for (int mt = 0; mt < 4; mt++) {
            #pragma unroll
            for (int nt = 0; nt < 4; nt++) {
                float v0 = fmaxf(acc[mt][nt][0], acc[mt][nt][1]);
                float v1 = fmaxf(acc[mt][nt][2], acc[mt][nt][3]);
                v0 = fmaxf(v0, __shfl_xor_sync(0xffffffffu, v0, 1));
                v0 = fmaxf(v0, __shfl_xor_sync(0xffffffffu, v0, 2));
                v1 = fmaxf(v1, __shfl_xor_sync(0xffffffffu, v1, 1));
                v1 = fmaxf(v1, __shfl_xor_sync(0xffffffffu, v1, 2));
                int cls = (n0 + wc * 32 + nt * 8) >> 3;
                if (qc == 0 && cls < NC) {
                    int r0 = m0 + wr * 64 + mt * 16 + qr;
                    g_cs[(size_t)r0 * NC + cls] = v0;
                    g_cs[(size_t)(r0 + 8) * NC + cls] = v1;
                }
            }
        }
    } else {
        float* Y = (MODE == 1) ? g_y1 : g_y2;
        #pragma unroll
        for (int mt = 0; mt < 4; mt++) {
            int r0 = m0 + wr * 64 + mt * 16 + qr;
            #pragma unroll
            for (int nt = 0; nt < 4; nt++) {
                int ncol = n0 + wc * 32 + nt * 8 + qc * 2;
                *(float2*)(Y + (size_t)r0 * ND + ncol) =
                    make_float2(acc[mt][nt][0], acc[mt][nt][1]);
                *(float2*)(Y + (size_t)(r0 + 8) * ND + ncol) =
                    make_float2(acc[mt][nt][2], acc[mt][nt][3]);
            }
        }
    }
}

// ================= proxy loss (b0 = batch-row offset) =======================
__global__ void __launch_bounds__(256) k_proxy_loss(const int* __restrict__ labels, int b0) {
    int b = b0 + blockIdx.x, tid = threadIdx.x;
    int lbl = labels[b];
    const float* row = g_cs + (size_t)b * NC;
    float lm = -3.4e38f;
    for (int i = tid; i < NC; i += 256) {
        float l = row[i];
        if (i == lbl) l -= MARGIN;
        lm = fmaxf(lm, l * INV_TEMP);
    }
    lm = block_reduce_max(lm);
    float se = 0.0f;
    for (int i = tid; i < NC; i += 256) {
        float l = row[i];
        if (i == lbl) l -= MARGIN;
        se += expf(l * INV_TEMP - lm);
    }
    se = block_reduce_sum(se);
    if (tid == 0) {
        float logit_lbl = (row[lbl] - MARGIN) * INV_TEMP;
        atomicAdd(&g_acc[0], (logf(se) + lm) - logit_lbl);
    }
}

// ================= enc LN + ReLU + proxy attention (bf16 P, smem-cached) ====
__global__ void __launch_bounds__(256) k_ln_att(const float* __restrict__ enc_b,
                                                const float* __restrict__ enc_g,
                                                const float* __restrict__ enc_beta,
                                                const int* __restrict__ labels) {
    int b = blockIdx.x, tid = threadIdx.x;
    __shared__ float e[ND];
    __shared__ float Ps[NP * ND];
    __shared__ float sdot[NP];
    const __nv_bfloat16* P = g_pB + (size_t)labels[b] * (NP * ND);
    #pragma unroll
    for (int r = 0; r < NP * 2; r++) {
        int i = tid + r * 256;
        __nv_bfloat162 p2 = *(const __nv_bfloat162*)(P + i * 2);
        Ps[i * 2]     = __bfloat162float(p2.x);
        Ps[i * 2 + 1] = __bfloat162float(p2.y);
    }

    float v[4], s = 0.0f, s2 = 0.0f;
    #pragma unroll
    for (int r = 0; r < 4; r++) {
        int i = tid + r * 256;
        float x = g_y1[(size_t)b * ND + i] + enc_b[i];
        v[r] = x; s += x; s2 += x * x;
    }
    s = block_reduce_sum(s);
    s2 = block_reduce_sum(s2);
    float mean = s * (1.0f / ND);
    float var = s2 * (1.0f / ND) - mean * mean;
    float rs = rsqrtf(var + 1e-5f);
    #pragma unroll
    for (int r = 0; r < 4; r++) {
        int i = tid + r * 256;
        e[i] = fmaxf((v[r] - mean) * rs * enc_g[i] + enc_beta[i], 0.0f);
    }
    __syncthreads();

    float part[NP];
    #pragma unroll
    for (int p = 0; p < NP; p++) part[p] = 0.0f;
    #pragma unroll
    for (int r = 0; r < 4; r++) {
        int i = tid + r * 256;
        float ev = e[i];
        #pragma unroll
        for (int p = 0; p < NP; p++) part[p] += Ps[p * ND + i] * ev;
    }
    #pragma unroll
    for (int p = 0; p < NP; p++) {
        float d = block_reduce_sum(part[p]);
        if (tid == 0) sdot[p] = d;
    }
    __syncthreads();

    float m = -3.4e38f;
    #pragma unroll
    for (int p = 0; p < NP; p++) m = fmaxf(m, sdot[p] * INV_TEMP);
    float w[NP], ws = 0.0f;
    #pragma unroll
    for (int p = 0; p < NP; p++) { w[p] = expf(sdot[p] * INV_TEMP - m); ws += w[p]; }
    float inv_ws = 1.0f / ws;
    #pragma unroll
    for (int r = 0; r < 4; r++) {
        int i = tid + r * 256;
        float c = 0.0f;
        #pragma unroll
        for (int p = 0; p < NP; p++) c += w[p] * Ps[p * ND + i];
        g_cA[(size_t)b * ND + i] = __float2bfloat16_rn(c * inv_ws);
    }
}

// ================= dec LN + masked recon loss ===============================
__global__ void __launch_bounds__(256) k_recon(const float* __restrict__ dec_b,
                                               const float* __restrict__ dec_g,
                                               const float* __restrict__ dec_beta,
                                               const float* __restrict__ features) {
    int b = blockIdx.x, tid = threadIdx.x;
    float v[4], s = 0.0f, s2 = 0.0f;
    #pragma unroll
    for (int r = 0; r < 4; r++) {
        int i = tid + r * 256;
        float x = g_y2[(size_t)b * ND + i] + dec_b[i];
        v[r] = x; s += x; s2 += x * x;
    }
    s = block_reduce_sum(s);
    s2 = block_reduce_sum(s2);
    float mean = s * (1.0f / ND);
    float var = s2 * (1.0f / ND) - mean * mean;
    float rs = rsqrtf(var + 1e-5f);
    float se = 0.0f;
    #pragma unroll
    for (int r = 0; r < 4; r++) {
        int i = tid + r * 256;
        size_t idx = (size_t)b * ND + i;
        float recon = (v[r] - mean) * rs * dec_g[i] + dec_beta[i];
        float d = recon - features[idx];
        se += d * d * (1.0f - g_maskf[idx]);
    }
    se = block_reduce_sum(se);
    if (tid == 0) atomicAdd(&g_acc[1], se * (1.0f / (float)N_MASKED));
}

__global__ void k_final(float* __restrict__ out) {
    out[0] = (g_acc[0] + g_acc[1]) * (1.0f / (float)NB);
}

// ================= launch ===================================================
extern "C" void kernel_launch(void* const* d_in, const int* in_sizes, int n_in,
                              void* d_out, int out_size) {
    const float* features = (const float*)d_in[0];
    const float* proxies  = (const float*)d_in[1];
    const float* noise    = (const float*)d_in[2];
    const float* enc_w    = (const float*)d_in[3];
    const float* enc_b    = (const float*)d_in[4];
    const float* enc_g    = (const float*)d_in[5];
    const float* enc_beta = (const float*)d_in[6];
    const float* dec_w    = (const float*)d_in[7];
    const float* dec_b    = (const float*)d_in[8];
    const float* dec_g    = (const float*)d_in[9];
    const float* dec_beta = (const float*)d_in[10];
    const int*   labels   = (const int*)d_in[11];
    float* out = (float*)d_out;

    cudaFuncSetAttribute(k_gemm<0>, cudaFuncAttributeMaxDynamicSharedMemorySize, SMEM_GEMM);
    cudaFuncSetAttribute(k_gemm<1>, cudaFuncAttributeMaxDynamicSharedMemorySize, SMEM_GEMM);
    cudaFuncSetAttribute(k_gemm<2>, cudaFuncAttributeMaxDynamicSharedMemorySize, SMEM_GEMM);

    cudaStream_t s0 = 0;           // harness capture stream (legacy default)
    cudaStream_t s2, s3;
    cudaStreamCreateWithFlags(&s2, cudaStreamNonBlocking);
    cudaStreamCreateWithFlags(&s3, cudaStreamNonBlocking);
    cudaEvent_t ev_fork, ev_fm, ev_nor, ev_cw, ev_g0a, ev_join;
    cudaEventCreateWithFlags(&ev_fork, cudaEventDisableTiming);
    cudaEventCreateWithFlags(&ev_fm,   cudaEventDisableTiming);
    cudaEventCreateWithFlags(&ev_nor,  cudaEventDisableTiming);
    cudaEventCreateWithFlags(&ev_cw,   cudaEventDisableTiming);
    cudaEventCreateWithFlags(&ev_g0a,  cudaEventDisableTiming);
    cudaEventCreateWithFlags(&ev_join, cudaEventDisableTiming);

    // fork s2, s3 off the capture stream
    cudaEventRecord(ev_fork, s0);
    cudaStreamWaitEvent(s2, ev_fork, 0);
    cudaStreamWaitEvent(s3, ev_fork, 0);

    // s3: weight conversion (independent of everything else)
    k_conv_w<<<(ND * ND / 4 + 255) / 256, 256, 0, s3>>>(enc_w, dec_w);
    cudaEventRecord(ev_cw, s3);

    // s2: featmask (g_fA, g_mA, g_maskf, g_acc init)
    k_featmask<<<NB, 256, 0, s2>>>(features, noise);
    cudaEventRecord(ev_fm, s2);

    // main: norm_prox (g_pB)
    k_norm_prox<<<NCP, 256, 0, s0>>>(proxies);
    cudaEventRecord(ev_nor, s0);

    // chain A on main: sim GEMM split over M halves -> proxy loss split
    cudaStreamWaitEvent(s0, ev_fm, 0);
    k_gemm<0><<<dim3(63, 16), 256, SMEM_GEMM, s0>>>(0);       // rows [0, 2048)
    cudaEventRecord(ev_g0a, s0);
    k_gemm<0><<<dim3(63, 16), 256, SMEM_GEMM, s0>>>(2048);    // rows [2048, 4096)
    k_proxy_loss<<<NB / 2, 256, 0, s0>>>(labels, 2048);       // second half

    // chain B on s2: enc GEMM (needs g_mA + g_ewb) -> ln_att -> dec GEMM -> recon
    cudaStreamWaitEvent(s2, ev_cw, 0);
    k_gemm<1><<<dim3(8, 32), 256, SMEM_GEMM, s2>>>(0);
    cudaStreamWaitEvent(s2, ev_nor, 0);
    k_ln_att<<<NB, 256, 0, s2>>>(enc_b, enc_g, enc_beta, labels);
    k_gemm<2><<<dim3(8, 32), 256, SMEM_GEMM, s2>>>(0);
    k_recon<<<NB, 256, 0, s2>>>(dec_b, dec_g, dec_beta, features);
    // overlap first-half proxy loss with second-half sim GEMM
    cudaStreamWaitEvent(s2, ev_g0a, 0);
    k_proxy_loss<<<NB / 2, 256, 0, s2>>>(labels, 0);          // first half

    // join s2 back into the capture stream, then final reduce
    cudaEventRecord(ev_join, s2);
    cudaStreamWaitEvent(s0, ev_join, 0);
    k_final<<<1, 1, 0, s0>>>(out);

    cudaEventDestroy(ev_fork);
    cudaEventDestroy(ev_fm);
    cudaEventDestroy(ev_nor);
    cudaEventDestroy(ev_cw);
    cudaEventDestroy(ev_g0a);
    cudaEventDestroy(ev_join);
    cudaStreamDestroy(s2);
    cudaStreamDestroy(s3);
}

// round 16
// speedup vs baseline: 1.0263x; 1.0263x over previous
#include <cuda_runtime.h>
#include <cuda_bf16.h>
#include <math.h>
#include <stdint.h>

// Problem constants
#define NB 4096
#define ND 1024
#define NC 1000
#define NP 8
#define NCP 8000
#define LEN_KEEP 870
#define N_MASKED 154
#define INV_TEMP 10.0f
#define MARGIN 0.3f

// ================= scratch (device globals) =================================
__device__ __nv_bfloat16 g_fA[NB * ND];     // normalized features (bf16)
__device__ __nv_bfloat16 g_pB[NCP * ND];    // normalized proxies (bf16)
__device__ __nv_bfloat16 g_mA[NB * ND];     // masked features (bf16)
__device__ __nv_bfloat16 g_cA[NB * ND];     // attention-combined (bf16)
__device__ __nv_bfloat16 g_ewb[ND * ND];    // enc_w bf16
__device__ __nv_bfloat16 g_dwb[ND * ND];    // dec_w bf16
__device__ float g_cs[NB * NC];
__device__ float g_maskf[NB * ND];
__device__ float g_y1[NB * ND];
__device__ float g_y2[NB * ND];
__device__ float g_acc[2];

__device__ __forceinline__ uint32_t smem_u32(const void* p) {
    uint32_t a;
    asm("{ .reg .u64 t; cvta.to.shared.u64 t, %1; cvt.u32.u64 %0, t; }" : "=r"(a) : "l"(p));
    return a;
}

// ================= block reductions (blockDim == 256) =======================
__device__ __forceinline__ float block_reduce_sum(float v) {
    __shared__ float s_red[8];
    int tid = threadIdx.x;
    #pragma unroll
    for (int o = 16; o; o >>= 1) v += __shfl_xor_sync(0xffffffffu, v, o);
    __syncthreads();
    if ((tid & 31) == 0) s_red[tid >> 5] = v;
    __syncthreads();
    if (tid < 32) {
        float x = (tid < 8) ? s_red[tid] : 0.0f;
        #pragma unroll
        for (int o = 4; o; o >>= 1) x += __shfl_xor_sync(0xffffffffu, x, o);
        if (tid == 0) s_red[0] = x;
    }
    __syncthreads();
    float r = s_red[0];
    __syncthreads();
    return r;
}
__device__ __forceinline__ float block_reduce_max(float v) {
    __shared__ float s_red[8];
    int tid = threadIdx.x;
    #pragma unroll
    for (int o = 16; o; o >>= 1) v = fmaxf(v, __shfl_xor_sync(0xffffffffu, v, o));
    __syncthreads();
    if ((tid & 31) == 0) s_red[tid >> 5] = v;
    __syncthreads();
    if (tid < 32) {
        float x = (tid < 8) ? s_red[tid] : -3.4e38f;
        #pragma unroll
        for (int o = 4; o; o >>= 1) x = fmaxf(x, __shfl_xor_sync(0xffffffffu, x, o));
        if (tid == 0) s_red[0] = x;
    }
    __syncthreads();
    float r = s_red[0];
    __syncthreads();
    return r;
}

// ================= fused: init + feat normalize + mask ======================
__global__ void __launch_bounds__(256) k_featmask(const float* __restrict__ features,
                                                  const float* __restrict__ noise) {
    int row = blockIdx.x, tid = threadIdx.x;
    if (row == 0 && tid == 0) { g_acc[0] = 0.0f; g_acc[1] = 0.0f; }
    const float* s = features + (size_t)row * ND;
    float v[4], ss = 0.0f;
    #pragma unroll
    for (int r = 0; r < 4; r++) { v[r] = s[tid + r * 256]; ss += v[r] * v[r]; }
    ss = block_reduce_sum(ss);
    float scale = 1.0f / fmaxf(sqrtf(ss), 1e-12f);
    #pragma unroll
    for (int r = 0; r < 4; r++)
        g_fA[(size_t)row * ND + tid + r * 256] = __float2bfloat16_rn(v[r] * scale);

    // radix select on noise bits (positive floats: bit order == value order)
    __shared__ unsigned sh[ND];
    __shared__ int hist[256];
    __shared__ int sel_digit, sel_rem, s_cl;
    const unsigned* nrow = (const unsigned*)noise + (size_t)row * ND;
    for (int i = tid; i < ND; i += 256) sh[i] = nrow[i];
    __syncthreads();

    unsigned prefix = 0;
    int remaining = LEN_KEEP - 1;
    for (int shift = 24; shift >= 0; shift -= 8) {
        hist[tid] = 0;
        __syncthreads();
        unsigned pmask = (shift == 24) ? 0u : (0xFFFFFFFFu << (shift + 8));
        for (int i = tid; i < ND; i += 256) {
            unsigned w = sh[i];
            if ((w & pmask) == prefix) atomicAdd(&hist[(w >> shift) & 0xFF], 1);
        }
        __syncthreads();
        if (tid == 0) {
            int cum = 0, d = 0;
            for (; d < 256; d++) {
                int h = hist[d];
                if (cum + h > remaining) break;
                cum += h;
            }
            sel_digit = d; sel_rem = remaining - cum;
        }
        __syncthreads();
        prefix |= ((unsigned)sel_digit) << shift;
        remaining = sel_rem;
        __syncthreads();
    }
    unsigned T = prefix;

    if (tid == 0) s_cl = 0;
    __syncthreads();
    int local = 0;
    for (int i = tid; i < ND; i += 256) if (sh[i] < T) local++;
    atomicAdd(&s_cl, local);
    __syncthreads();
    int quota = LEN_KEEP - s_cl;

    #pragma unroll
    for (int r = 0; r < 4; r++) {
        int i = tid + r * 256;
        unsigned w = sh[i];
        float m;
        if (w < T) m = 1.0f;
        else if (w > T) m = 0.0f;
        else {
            int rk = 0;
            for (int j = 0; j < i; j++) rk += (sh[j] == T) ? 1 : 0;
            m = (rk < quota) ? 1.0f : 0.0f;
        }
        size_t idx = (size_t)row * ND + i;
        g_maskf[idx] = m;
        g_mA[idx] = __float2bfloat16_rn(v[r] * m);
    }
}

__global__ void __launch_bounds__(256) k_norm_prox(const float* __restrict__ src) {
    int row = blockIdx.x, tid = threadIdx.x;
    const float* s = src + (size_t)row * ND;
    float v[4], ss = 0.0f;
    #pragma unroll
    for (int r = 0; r < 4; r++) { v[r] = s[tid + r * 256]; ss += v[r] * v[r]; }
    ss = block_reduce_sum(ss);
    float scale = 1.0f / fmaxf(sqrtf(ss), 1e-12f);
    #pragma unroll
    for (int r = 0; r < 4; r++) {
        size_t i = (size_t)row * ND + tid + r * 256;
        g_pB[i] = __float2bfloat16_rn(v[r] * scale);
    }
}

__global__ void __launch_bounds__(256) k_conv_w(const float* __restrict__ ew,
                                                const float* __restrict__ dw) {
    int i0 = (blockIdx.x * 256 + threadIdx.x) * 4;
    if (i0 < ND * ND) {
        float4 e4 = *(const float4*)(ew + i0);
        float4 d4 = *(const float4*)(dw + i0);
        __nv_bfloat162 e01 = {__float2bfloat16_rn(e4.x), __float2bfloat16_rn(e4.y)};
        __nv_bfloat162 e23 = {__float2bfloat16_rn(e4.z), __float2bfloat16_rn(e4.w)};
        __nv_bfloat162 d01 = {__float2bfloat16_rn(d4.x), __float2bfloat16_rn(d4.y)};
        __nv_bfloat162 d23 = {__float2bfloat16_rn(d4.z), __float2bfloat16_rn(d4.w)};
        *(__nv_bfloat162*)(g_ewb + i0) = e01;
        *(__nv_bfloat162*)(g_ewb + i0 + 2) = e23;
        *(__nv_bfloat162*)(g_dwb + i0) = d01;
        *(__nv_bfloat162*)(g_dwb + i0 + 2) = d23;
    }
}

// ================= HMMA bf16 GEMM: C[M,N] = A[M,K] * B[N,K]^T ===============
// 128x128 block tile, BK=64, 256 thr (8 warps 2x4), warp 64x32 = 4x4 m16n8k16
// 2-stage cp.async double buffer, single leading barrier per chunk.
#define RSTRIDE_B 144                 // bytes per SMEM row (64 bf16 + 8 pad)
#define TILE_BYTES (128 * RSTRIDE_B)  // 18432
#define STAGE_BYTES (2 * TILE_BYTES)  // A+B = 36864
#define SMEM_GEMM (2 * STAGE_BYTES)   // 73728

template <int MODE>
__global__ void __launch_bounds__(256, 2) k_gemm(int mrow0) {
    extern __shared__ __align__(16) char smem[];
    const __nv_bfloat16* A = (MODE == 0) ? g_fA : (MODE == 1) ? g_mA : g_cA;
    const __nv_bfloat16* B = (MODE == 0) ? g_pB : (MODE == 1) ? g_ewb : g_dwb;
    const int nrowsB = (MODE == 0) ? NCP : ND;

    int tid = threadIdx.x, lane = tid & 31, wid = tid >> 5;
    int wr = wid & 1, wc = wid >> 1;
    int m0 = mrow0 + blockIdx.y * 128, n0 = blockIdx.x * 128;
    uint32_t sb = smem_u32(smem);

    int aRow = (lane & 7) | (((lane >> 3) & 1) << 3);
    uint32_t aOffBase = (uint32_t)((wr * 64 + aRow) * RSTRIDE_B + (lane >> 4) * 16);
    int bRow = (lane & 7) + ((lane >> 4) << 3);
    uint32_t bOffBase = (uint32_t)((wc * 32 + bRow) * RSTRIDE_B + ((lane >> 3) & 1) * 16);

    float acc[4][4][4];
    #pragma unroll
    for (int i = 0; i < 4; i++)
        #pragma unroll
        for (int j = 0; j < 4; j++)
            #pragma unroll
            for (int q = 0; q < 4; q++) acc[i][j][q] = 0.0f;

    const int NCHUNK = ND / 64;   // 16

    auto load_chunk = [&](int c, int buf) {
        int kb = c * 64;
        uint32_t a_s = sb + (uint32_t)(buf * STAGE_BYTES);
        uint32_t b_s = a_s + TILE_BYTES;
        #pragma unroll
        for (int j = 0; j < 4; j++) {
            int u = tid + j * 256;
            int row = u >> 3, seg = u & 7;
            uint32_t sa = a_s + row * RSTRIDE_B + seg * 16;
            const void* ga = A + (size_t)(m0 + row) * ND + kb + seg * 8;
            asm volatile("cp.async.cg.shared.global [%0], [%1], 16;" :: "r"(sa), "l"(ga));
        }
        #pragma unroll
        for (int j = 0; j < 4; j++) {
            int u = tid + j * 256;
            int row = u >> 3, seg = u & 7;
            int grow = n0 + row;
            uint32_t sbb = b_s + row * RSTRIDE_B + seg * 16;
            const void* gb = B + (size_t)(grow < nrowsB ? grow : 0) * ND + kb + seg * 8;
            int srcsz = (grow < nrowsB) ? 16 : 0;
            asm volatile("cp.async.cg.shared.global [%0], [%1], 16, %2;" :: "r"(sbb), "l"(gb), "r"(srcsz));
        }
        asm volatile("cp.async.commit_group;" ::: "memory");
    };

    load_chunk(0, 0);
    for (int c = 0; c < NCHUNK; c++) {
        asm volatile("cp.async.wait_group 0;" ::: "memory");
        __syncthreads();
        if (c + 1 < NCHUNK) load_chunk(c + 1, (c + 1) & 1);
        uint32_t a_s = sb + (uint32_t)((c & 1) * STAGE_BYTES);
        uint32_t b_s = a_s + TILE_BYTES;
        #pragma unroll
        for (int kk = 0; kk < 4; kk++) {
            uint32_t afr[4][4], bfr[4][2];
            #pragma unroll
            for (int mt = 0; mt < 4; mt++) {
                uint32_t ad = a_s + aOffBase + mt * 16 * RSTRIDE_B + kk * 32;
                asm volatile("ldmatrix.sync.aligned.m8n8.x4.shared.b16 {%0,%1,%2,%3}, [%4];"
                             : "=r"(afr[mt][0]), "=r"(afr[mt][1]), "=r"(afr[mt][2]), "=r"(afr[mt][3])
                             : "r"(ad));
            }
            #pragma unroll
            for (int ntp = 0; ntp < 2; ntp++) {
                uint32_t bd = b_s + bOffBase + ntp * 16 * RSTRIDE_B + kk * 32;
                asm volatile("ldmatrix.sync.aligned.m8n8.x4.shared.b16 {%0,%1,%2,%3}, [%4];"
                             : "=r"(bfr[2 * ntp][0]), "=r"(bfr[2 * ntp][1]),
                               "=r"(bfr[2 * ntp + 1][0]), "=r"(bfr[2 * ntp + 1][1])
                             : "r"(bd));
            }
            #pragma unroll
            for (int mt = 0; mt < 4; mt++)
                #pragma unroll
                for (int nt = 0; nt < 4; nt++)
                    asm volatile("mma.sync.aligned.m16n8k16.row.col.f32.bf16.bf16.f32 "
                                 "{%0,%1,%2,%3}, {%4,%5,%6,%7}, {%8,%9}, {%0,%1,%2,%3};"
                                 : "+f"(acc[mt][nt][0]), "+f"(acc[mt][nt][1]),
                                   "+f"(acc[mt][nt][2]), "+f"(acc[mt][nt][3])
                                 : "r"(afr[mt][0]), "r"(afr[mt][1]), "r"(afr[mt][2]), "r"(afr[mt][3]),
                                   "r"(bfr[nt][0]), "r"(bfr[nt][1]));
        }
    }

    int qr = lane >> 2, qc = lane & 3;
    if (MODE == 0) {
        #pragma unroll
        for (int mt = 0; mt < 4; mt++) {
            #pragma unroll
            for (int nt = 0; nt < 4; nt++) {
                float v0 = fmaxf(acc[mt][nt][0], acc[mt][nt][1]);
                float v1 = fmaxf(acc[mt][nt][2], acc[mt][nt][3]);
                v0 = fmaxf(v0, __shfl_xor_sync(0xffffffffu, v0, 1));
                v0 = fmaxf(v0, __shfl_xor_sync(0xffffffffu, v0, 2));
                v1 = fmaxf(v1, __shfl_xor_sync(0xffffffffu, v1, 1));
                v1 = fmaxf(v1, __shfl_xor_sync(0xffffffffu, v1, 2));
                int cls = (n0 + wc * 32 + nt * 8) >> 3;
                if (qc == 0 && cls < NC) {
                    int r0 = m0 + wr * 64 + mt * 16 + qr;
                    g_cs[(size_t)r0 * NC + cls] = v0;
                    g_cs[(size_t)(r0 + 8) * NC + cls] = v1;
                }
            }
        }
    } else {
        float* Y = (MODE == 1) ? g_y1 : g_y2;
        #pragma unroll
        for (int mt = 0; mt < 4; mt++) {
            int r0 = m0 + wr * 64 + mt * 16 + qr;
            #pragma unroll
            for (int nt = 0; nt < 4; nt++) {
                int ncol = n0 + wc * 32 + nt * 8 + qc * 2;
                *(float2*)(Y + (size_t)r0 * ND + ncol) =
                    make_float2(acc[mt][nt][0], acc[mt][nt][1]);
                *(float2*)(Y + (size_t)(r0 + 8) * ND + ncol) =
                    make_float2(acc[mt][nt][2], acc[mt][nt][3]);
            }
        }
    }
}

// ================= proxy loss (b0 = batch-row offset) =======================
__global__ void __launch_bounds__(256) k_proxy_loss(const int* __restrict__ labels, int b0) {
    int b = b0 + blockIdx.x, tid = threadIdx.x;
    int lbl = labels[b];
    const float* row = g_cs + (size_t)b * NC;
    float lm = -3.4e38f;
    for (int i = tid; i < NC; i += 256) {
        float l = row[i];
        if (i == lbl) l -= MARGIN;
        lm = fmaxf(lm, l * INV_TEMP);
    }
    lm = block_reduce_max(lm);
    float se = 0.0f;
    for (int i = tid; i < NC; i += 256) {
        float l = row[i];
        if (i == lbl) l -= MARGIN;
        se += expf(l * INV_TEMP - lm);
    }
    se = block_reduce_sum(se);
    if (tid == 0) {
        float logit_lbl = (row[lbl] - MARGIN) * INV_TEMP;
        atomicAdd(&g_acc[0], (logf(se) + lm) - logit_lbl);
    }
}

// ================= enc LN + ReLU + proxy attention (bf16 P, smem-cached) ====
__global__ void __launch_bounds__(256) k_ln_att(const float* __restrict__ enc_b,
                                                const float* __restrict__ enc_g,
                                                const float* __restrict__ enc_beta,
                                                const int* __restrict__ labels) {
    int b = blockIdx.x, tid = threadIdx.x;
    __shared__ float e[ND];
    __shared__ float Ps[NP * ND];
    __shared__ float sdot[NP];
    const __nv_bfloat16* P = g_pB + (size_t)labels[b] * (NP * ND);
    #pragma unroll
    for (int r = 0; r < NP * 2; r++) {
        int i = tid + r * 256;
        __nv_bfloat162 p2 = *(const __nv_bfloat162*)(P + i * 2);
        Ps[i * 2]     = __bfloat162float(p2.x);
        Ps[i * 2 + 1] = __bfloat162float(p2.y);
    }

    float v[4], s = 0.0f, s2 = 0.0f;
    #pragma unroll
    for (int r = 0; r < 4; r++) {
        int i = tid + r * 256;
        float x = g_y1[(size_t)b * ND + i] + enc_b[i];
        v[r] = x; s += x; s2 += x * x;
    }
    s = block_reduce_sum(s);
    s2 = block_reduce_sum(s2);
    float mean = s * (1.0f / ND);
    float var = s2 * (1.0f / ND) - mean * mean;
    float rs = rsqrtf(var + 1e-5f);
    #pragma unroll
    for (int r = 0; r < 4; r++) {
        int i = tid + r * 256;
        e[i] = fmaxf((v[r] - mean) * rs * enc_g[i] + enc_beta[i], 0.0f);
    }
    __syncthreads();

    float part[NP];
    #pragma unroll
    for (int p = 0; p < NP; p++) part[p] = 0.0f;
    #pragma unroll
    for (int r = 0; r < 4; r++) {
        int i = tid + r * 256;
        float ev = e[i];
        #pragma unroll
        for (int p = 0; p < NP; p++) part[p] += Ps[p * ND + i] * ev;
    }
    #pragma unroll
    for (int p = 0; p < NP; p++) {
        float d = block_reduce_sum(part[p]);
        if (tid == 0) sdot[p] = d;
    }
    __syncthreads();

    float m = -3.4e38f;
    #pragma unroll
    for (int p = 0; p < NP; p++) m = fmaxf(m, sdot[p] * INV_TEMP);
    float w[NP], ws = 0.0f;
    #pragma unroll
    for (int p = 0; p < NP; p++) { w[p] = expf(sdot[p] * INV_TEMP - m); ws += w[p]; }
    float inv_ws = 1.0f / ws;
    #pragma unroll
    for (int r = 0; r < 4; r++) {
        int i = tid + r * 256;
        float c = 0.0f;
        #pragma unroll
        for (int p = 0; p < NP; p++) c += w[p] * Ps[p * ND + i];
        g_cA[(size_t)b * ND + i] = __float2bfloat16_rn(c * inv_ws);
    }
}

// ================= dec LN + masked recon loss ===============================
__global__ void __launch_bounds__(256) k_recon(const float* __restrict__ dec_b,
                                               const float* __restrict__ dec_g,
                                               const float* __restrict__ dec_beta,
                                               const float* __restrict__ features) {
    int b = blockIdx.x, tid = threadIdx.x;
    float v[4], s = 0.0f, s2 = 0.0f;
    #pragma unroll
    for (int r = 0; r < 4; r++) {
        int i = tid + r * 256;
        float x = g_y2[(size_t)b * ND + i] + dec_b[i];
        v[r] = x; s += x; s2 += x * x;
    }
    s = block_reduce_sum(s);
    s2 = block_reduce_sum(s2);
    float mean = s * (1.0f / ND);
    float var = s2 * (1.0f / ND) - mean * mean;
    float rs = rsqrtf(var + 1e-5f);
    float se = 0.0f;
    #pragma unroll
    for (int r = 0; r < 4; r++) {
        int i = tid + r * 256;
        size_t idx = (size_t)b * ND + i;
        float recon = (v[r] - mean) * rs * dec_g[i] + dec_beta[i];
        float d = recon - features[idx];
        se += d * d * (1.0f - g_maskf[idx]);
    }
    se = block_reduce_sum(se);
    if (tid == 0) atomicAdd(&g_acc[1], se * (1.0f / (float)N_MASKED));
}

__global__ void k_final(float* __restrict__ out) {
    out[0] = (g_acc[0] + g_acc[1]) * (1.0f / (float)NB);
}

// ================= launch ===================================================
extern "C" void kernel_launch(void* const* d_in, const int* in_sizes, int n_in,
                              void* d_out, int out_size) {
    const float* features = (const float*)d_in[0];
    const float* proxies  = (const float*)d_in[1];
    const float* noise    = (const float*)d_in[2];
    const float* enc_w    = (const float*)d_in[3];
    const float* enc_b    = (const float*)d_in[4];
    const float* enc_g    = (const float*)d_in[5];
    const float* enc_beta = (const float*)d_in[6];
    const float* dec_w    = (const float*)d_in[7];
    const float* dec_b    = (const float*)d_in[8];
    const float* dec_g    = (const float*)d_in[9];
    const float* dec_beta = (const float*)d_in[10];
    const int*   labels   = (const int*)d_in[11];
    float* out = (float*)d_out;

    cudaFuncSetAttribute(k_gemm<0>, cudaFuncAttributeMaxDynamicSharedMemorySize, SMEM_GEMM);
    cudaFuncSetAttribute(k_gemm<1>, cudaFuncAttributeMaxDynamicSharedMemorySize, SMEM_GEMM);
    cudaFuncSetAttribute(k_gemm<2>, cudaFuncAttributeMaxDynamicSharedMemorySize, SMEM_GEMM);

    cudaStream_t s0 = 0;           // harness capture stream (legacy default)
    cudaStream_t s2;
    cudaStreamCreateWithFlags(&s2, cudaStreamNonBlocking);
    cudaEvent_t ev_fork, ev_fm, ev_nor, ev_g0a, ev_join;
    cudaEventCreateWithFlags(&ev_fork, cudaEventDisableTiming);
    cudaEventCreateWithFlags(&ev_fm,   cudaEventDisableTiming);
    cudaEventCreateWithFlags(&ev_nor,  cudaEventDisableTiming);
    cudaEventCreateWithFlags(&ev_g0a,  cudaEventDisableTiming);
    cudaEventCreateWithFlags(&ev_join, cudaEventDisableTiming);

    // fork s2 off the capture stream
    cudaEventRecord(ev_fork, s0);
    cudaStreamWaitEvent(s2, ev_fork, 0);

    // s2: featmask (g_fA, g_mA, g_maskf, g_acc init) then conv_w (weights)
    k_featmask<<<NB, 256, 0, s2>>>(features, noise);
    cudaEventRecord(ev_fm, s2);
    k_conv_w<<<(ND * ND / 4 + 255) / 256, 256, 0, s2>>>(enc_w, dec_w);

    // main: norm_prox (g_pB)
    k_norm_prox<<<NCP, 256, 0, s0>>>(proxies);
    cudaEventRecord(ev_nor, s0);

    // chain A on main: sim GEMM split over M halves -> proxy loss split
    cudaStreamWaitEvent(s0, ev_fm, 0);
    k_gemm<0><<<dim3(63, 16), 256, SMEM_GEMM, s0>>>(0);       // rows [0, 2048)
    cudaEventRecord(ev_g0a, s0);
    k_gemm<0><<<dim3(63, 16), 256, SMEM_GEMM, s0>>>(2048);    // rows [2048, 4096)
    k_proxy_loss<<<NB / 2, 256, 0, s0>>>(labels, 2048);       // second half

    // chain B on s2: enc GEMM -> ln_att (needs g_pB) -> dec GEMM -> recon
    k_gemm<1><<<dim3(8, 32), 256, SMEM_GEMM, s2>>>(0);
    cudaStreamWaitEvent(s2, ev_nor, 0);
    k_ln_att<<<NB, 256, 0, s2>>>(enc_b, enc_g, enc_beta, labels);
    k_gemm<2><<<dim3(8, 32), 256, SMEM_GEMM, s2>>>(0);
    k_recon<<<NB, 256, 0, s2>>>(dec_b, dec_g, dec_beta, features);
    // overlap first-half proxy loss with second-half sim GEMM
    cudaStreamWaitEvent(s2, ev_g0a, 0);
    k_proxy_loss<<<NB / 2, 256, 0, s2>>>(labels, 0);          // first half

    // join s2 back into the capture stream, then final reduce
    cudaEventRecord(ev_join, s2);
    cudaStreamWaitEvent(s0, ev_join, 0);
    k_final<<<1, 1, 0, s0>>>(out);

    cudaEventDestroy(ev_fork);
    cudaEventDestroy(ev_fm);
    cudaEventDestroy(ev_nor);
    cudaEventDestroy(ev_g0a);
    cudaEventDestroy(ev_join);
    cudaStreamDestroy(s2);
}

// round 17
// speedup vs baseline: 1.0285x; 1.0021x over previous
#include <cuda_runtime.h>
#include <cuda_bf16.h>
#include <math.h>
#include <stdint.h>

// Problem constants
#define NB 4096
#define ND 1024
#define NC 1000
#define NP 8
#define NCP 8000
#define LEN_KEEP 870
#define N_MASKED 154
#define INV_TEMP 10.0f
#define MARGIN 0.3f

// ================= scratch (device globals) =================================
__device__ __nv_bfloat16 g_fA[NB * ND];     // normalized features (bf16)
__device__ __nv_bfloat16 g_pB[NCP * ND];    // normalized proxies (bf16)
__device__ __nv_bfloat16 g_mA[NB * ND];     // masked features (bf16)
__device__ __nv_bfloat16 g_cA[NB * ND];     // attention-combined (bf16)
__device__ __nv_bfloat16 g_ewb[ND * ND];    // enc_w bf16
__device__ __nv_bfloat16 g_dwb[ND * ND];    // dec_w bf16
__device__ float g_cs[NB * NC];
__device__ unsigned g_mbits[NB * (ND / 32)]; // packed keep-mask (1 = kept)
__device__ float g_y1[NB * ND];
__device__ float g_y2[NB * ND];
__device__ float g_acc[2];

__device__ __forceinline__ uint32_t smem_u32(const void* p) {
    uint32_t a;
    asm("{ .reg .u64 t; cvta.to.shared.u64 t, %1; cvt.u32.u64 %0, t; }" : "=r"(a) : "l"(p));
    return a;
}

// ================= block reductions (blockDim == 256) =======================
__device__ __forceinline__ float block_reduce_sum(float v) {
    __shared__ float s_red[8];
    int tid = threadIdx.x;
    #pragma unroll
    for (int o = 16; o; o >>= 1) v += __shfl_xor_sync(0xffffffffu, v, o);
    __syncthreads();
    if ((tid & 31) == 0) s_red[tid >> 5] = v;
    __syncthreads();
    if (tid < 32) {
        float x = (tid < 8) ? s_red[tid] : 0.0f;
        #pragma unroll
        for (int o = 4; o; o >>= 1) x += __shfl_xor_sync(0xffffffffu, x, o);
        if (tid == 0) s_red[0] = x;
    }
    __syncthreads();
    float r = s_red[0];
    __syncthreads();
    return r;
}
__device__ __forceinline__ float block_reduce_max(float v) {
    __shared__ float s_red[8];
    int tid = threadIdx.x;
    #pragma unroll
    for (int o = 16; o; o >>= 1) v = fmaxf(v, __shfl_xor_sync(0xffffffffu, v, o));
    __syncthreads();
    if ((tid & 31) == 0) s_red[tid >> 5] = v;
    __syncthreads();
    if (tid < 32) {
        float x = (tid < 8) ? s_red[tid] : -3.4e38f;
        #pragma unroll
        for (int o = 4; o; o >>= 1) x = fmaxf(x, __shfl_xor_sync(0xffffffffu, x, o));
        if (tid == 0) s_red[0] = x;
    }
    __syncthreads();
    float r = s_red[0];
    __syncthreads();
    return r;
}

// ================= fused: init + feat normalize + mask ======================
__global__ void __launch_bounds__(256) k_featmask(const float* __restrict__ features,
                                                  const float* __restrict__ noise) {
    int row = blockIdx.x, tid = threadIdx.x;
    if (row == 0 && tid == 0) { g_acc[0] = 0.0f; g_acc[1] = 0.0f; }
    const float* s = features + (size_t)row * ND;
    float v[4], ss = 0.0f;
    #pragma unroll
    for (int r = 0; r < 4; r++) { v[r] = s[tid + r * 256]; ss += v[r] * v[r]; }
    ss = block_reduce_sum(ss);
    float scale = 1.0f / fmaxf(sqrtf(ss), 1e-12f);
    #pragma unroll
    for (int r = 0; r < 4; r++)
        g_fA[(size_t)row * ND + tid + r * 256] = __float2bfloat16_rn(v[r] * scale);

    // radix select on noise bits (positive floats: bit order == value order)
    __shared__ unsigned sh[ND];
    __shared__ int hist[256];
    __shared__ int sel_digit, sel_rem, s_cl;
    const unsigned* nrow = (const unsigned*)noise + (size_t)row * ND;
    for (int i = tid; i < ND; i += 256) sh[i] = nrow[i];
    __syncthreads();

    unsigned prefix = 0;
    int remaining = LEN_KEEP - 1;
    for (int shift = 24; shift >= 0; shift -= 8) {
        hist[tid] = 0;
        __syncthreads();
        unsigned pmask = (shift == 24) ? 0u : (0xFFFFFFFFu << (shift + 8));
        for (int i = tid; i < ND; i += 256) {
            unsigned w = sh[i];
            if ((w & pmask) == prefix) atomicAdd(&hist[(w >> shift) & 0xFF], 1);
        }
        __syncthreads();
        if (tid == 0) {
            int cum = 0, d = 0;
            for (; d < 256; d++) {
                int h = hist[d];
                if (cum + h > remaining) break;
                cum += h;
            }
            sel_digit = d; sel_rem = remaining - cum;
        }
        __syncthreads();
        prefix |= ((unsigned)sel_digit) << shift;
        remaining = sel_rem;
        __syncthreads();
    }
    unsigned T = prefix;

    if (tid == 0) s_cl = 0;
    __syncthreads();
    int local = 0;
    for (int i = tid; i < ND; i += 256) if (sh[i] < T) local++;
    atomicAdd(&s_cl, local);
    __syncthreads();
    int quota = LEN_KEEP - s_cl;

    #pragma unroll
    for (int r = 0; r < 4; r++) {
        int i = tid + r * 256;
        unsigned w = sh[i];
        float m;
        if (w < T) m = 1.0f;
        else if (w > T) m = 0.0f;
        else {
            int rk = 0;
            for (int j = 0; j < i; j++) rk += (sh[j] == T) ? 1 : 0;
            m = (rk < quota) ? 1.0f : 0.0f;
        }
        // packed mask: bit (i & 31) of word (i >> 5); warp lanes are consecutive
        unsigned bal = __ballot_sync(0xffffffffu, m > 0.5f);
        if ((tid & 31) == 0)
            g_mbits[(size_t)row * (ND / 32) + (i >> 5)] = bal;
        size_t idx = (size_t)row * ND + i;
        g_mA[idx] = __float2bfloat16_rn(v[r] * m);
    }
}

__global__ void __launch_bounds__(256) k_norm_prox(const float* __restrict__ src) {
    int row = blockIdx.x, tid = threadIdx.x;
    const float* s = src + (size_t)row * ND;
    float v[4], ss = 0.0f;
    #pragma unroll
    for (int r = 0; r < 4; r++) { v[r] = s[tid + r * 256]; ss += v[r] * v[r]; }
    ss = block_reduce_sum(ss);
    float scale = 1.0f / fmaxf(sqrtf(ss), 1e-12f);
    #pragma unroll
    for (int r = 0; r < 4; r++) {
        size_t i = (size_t)row * ND + tid + r * 256;
        g_pB[i] = __float2bfloat16_rn(v[r] * scale);
    }
}

__global__ void __launch_bounds__(256) k_conv_w(const float* __restrict__ ew,
                                                const float* __restrict__ dw) {
    int i0 = (blockIdx.x * 256 + threadIdx.x) * 4;
    if (i0 < ND * ND) {
        float4 e4 = *(const float4*)(ew + i0);
        float4 d4 = *(const float4*)(dw + i0);
        __nv_bfloat162 e01 = {__float2bfloat16_rn(e4.x), __float2bfloat16_rn(e4.y)};
        __nv_bfloat162 e23 = {__float2bfloat16_rn(e4.z), __float2bfloat16_rn(e4.w)};
        __nv_bfloat162 d01 = {__float2bfloat16_rn(d4.x), __float2bfloat16_rn(d4.y)};
        __nv_bfloat162 d23 = {__float2bfloat16_rn(d4.z), __float2bfloat16_rn(d4.w)};
        *(__nv_bfloat162*)(g_ewb + i0) = e01;
        *(__nv_bfloat162*)(g_ewb + i0 + 2) = e23;
        *(__nv_bfloat162*)(g_dwb + i0) = d01;
        *(__nv_bfloat162*)(g_dwb + i0 + 2) = d23;
    }
}

// ================= HMMA bf16 GEMM: C[M,N] = A[M,K] * B[N,K]^T ===============
// 128x128 block tile, BK=64, 256 thr (8 warps 2x4), warp 64x32 = 4x4 m16n8k16
// 2-stage cp.async double buffer, single leading barrier per chunk.
#define RSTRIDE_B 144                 // bytes per SMEM row (64 bf16 + 8 pad)
#define TILE_BYTES (128 * RSTRIDE_B)  // 18432
#define STAGE_BYTES (2 * TILE_BYTES)  // A+B = 36864
#define SMEM_GEMM (2 * STAGE_BYTES)   // 73728

template <int MODE>
__global__ void __launch_bounds__(256, 2) k_gemm(int mrow0) {
    extern __shared__ __align__(16) char smem[];
    const __nv_bfloat16* A = (MODE == 0) ? g_fA : (MODE == 1) ? g_mA : g_cA;
    const __nv_bfloat16* B = (MODE == 0) ? g_pB : (MODE == 1) ? g_ewb : g_dwb;
    const int nrowsB = (MODE == 0) ? NCP : ND;

    int tid = threadIdx.x, lane = tid & 31, wid = tid >> 5;
    int wr = wid & 1, wc = wid >> 1;
    int m0 = mrow0 + blockIdx.y * 128, n0 = blockIdx.x * 128;
    uint32_t sb = smem_u32(smem);

    int aRow = (lane & 7) | (((lane >> 3) & 1) << 3);
    uint32_t aOffBase = (uint32_t)((wr * 64 + aRow) * RSTRIDE_B + (lane >> 4) * 16);
    int bRow = (lane & 7) + ((lane >> 4) << 3);
    uint32_t bOffBase = (uint32_t)((wc * 32 + bRow) * RSTRIDE_B + ((lane >> 3) & 1) * 16);

    float acc[4][4][4];
    #pragma unroll
    for (int i = 0; i < 4; i++)
        #pragma unroll
        for (int j = 0; j < 4; j++)
            #pragma unroll
            for (int q = 0; q < 4; q++) acc[i][j][q] = 0.0f;

    const int NCHUNK = ND / 64;   // 16

    auto load_chunk = [&](int c, int buf) {
        int kb = c * 64;
        uint32_t a_s = sb + (uint32_t)(buf * STAGE_BYTES);
        uint32_t b_s = a_s + TILE_BYTES;
        #pragma unroll
        for (int j = 0; j < 4; j++) {
            int u = tid + j * 256;
            int row = u >> 3, seg = u & 7;
            uint32_t sa = a_s + row * RSTRIDE_B + seg * 16;
            const void* ga = A + (size_t)(m0 + row) * ND + kb + seg * 8;
            asm volatile("cp.async.cg.shared.global [%0], [%1], 16;" :: "r"(sa), "l"(ga));
        }
        #pragma unroll
        for (int j = 0; j < 4; j++) {
            int u = tid + j * 256;
            int row = u >> 3, seg = u & 7;
            int grow = n0 + row;
            uint32_t sbb = b_s + row * RSTRIDE_B + seg * 16;
            const void* gb = B + (size_t)(grow < nrowsB ? grow : 0) * ND + kb + seg * 8;
            int srcsz = (grow < nrowsB) ? 16 : 0;
            asm volatile("cp.async.cg.shared.global [%0], [%1], 16, %2;" :: "r"(sbb), "l"(gb), "r"(srcsz));
        }
        asm volatile("cp.async.commit_group;" ::: "memory");
    };

    load_chunk(0, 0);
    for (int c = 0; c < NCHUNK; c++) {
        asm volatile("cp.async.wait_group 0;" ::: "memory");
        __syncthreads();
        if (c + 1 < NCHUNK) load_chunk(c + 1, (c + 1) & 1);
        uint32_t a_s = sb + (uint32_t)((c & 1) * STAGE_BYTES);
        uint32_t b_s = a_s + TILE_BYTES;
        #pragma unroll
        for (int kk = 0; kk < 4; kk++) {
            uint32_t afr[4][4], bfr[4][2];
            #pragma unroll
            for (int mt = 0; mt < 4; mt++) {
                uint32_t ad = a_s + aOffBase + mt * 16 * RSTRIDE_B + kk * 32;
                asm volatile("ldmatrix.sync.aligned.m8n8.x4.shared.b16 {%0,%1,%2,%3}, [%4];"
                             : "=r"(afr[mt][0]), "=r"(afr[mt][1]), "=r"(afr[mt][2]), "=r"(afr[mt][3])
                             : "r"(ad));
            }
            #pragma unroll
            for (int ntp = 0; ntp < 2; ntp++) {
                uint32_t bd = b_s + bOffBase + ntp * 16 * RSTRIDE_B + kk * 32;
                asm volatile("ldmatrix.sync.aligned.m8n8.x4.shared.b16 {%0,%1,%2,%3}, [%4];"
                             : "=r"(bfr[2 * ntp][0]), "=r"(bfr[2 * ntp][1]),
                               "=r"(bfr[2 * ntp + 1][0]), "=r"(bfr[2 * ntp + 1][1])
                             : "r"(bd));
            }
            #pragma unroll
            for (int mt = 0; mt < 4; mt++)
                #pragma unroll
                for (int nt = 0; nt < 4; nt++)
                    asm volatile("mma.sync.aligned.m16n8k16.row.col.f32.bf16.bf16.f32 "
                                 "{%0,%1,%2,%3}, {%4,%5,%6,%7}, {%8,%9}, {%0,%1,%2,%3};"
                                 : "+f"(acc[mt][nt][0]), "+f"(acc[mt][nt][1]),
                                   "+f"(acc[mt][nt][2]), "+f"(acc[mt][nt][3])
                                 : "r"(afr[mt][0]), "r"(afr[mt][1]), "r"(afr[mt][2]), "r"(afr[mt][3]),
                                   "r"(bfr[nt][0]), "r"(bfr[nt][1]));
        }
    }

    int qr = lane >> 2, qc = lane & 3;
    if (MODE == 0) {
        #pragma unroll
        for (int mt = 0; mt < 4; mt++) {
            #pragma unroll
            for (int nt = 0; nt < 4; nt++) {
                float v0 = fmaxf(acc[mt][nt][0], acc[mt][nt][1]);
                float v1 = fmaxf(acc[mt][nt][2], acc[mt][nt][3]);
                v0 = fmaxf(v0, __shfl_xor_sync(0xffffffffu, v0, 1));
                v0 = fmaxf(v0, __shfl_xor_sync(0xffffffffu, v0, 2));
                v1 = fmaxf(v1, __shfl_xor_sync(0xffffffffu, v1, 1));
                v1 = fmaxf(v1, __shfl_xor_sync(0xffffffffu, v1, 2));
                int cls = (n0 + wc * 32 + nt * 8) >> 3;
                if (qc == 0 && cls < NC) {
                    int r0 = m0 + wr * 64 + mt * 16 + qr;
                    g_cs[(size_t)r0 * NC + cls] = v0;
                    g_cs[(size_t)(r0 + 8) * NC + cls] = v1;
                }
            }
        }
    } else {
        float* Y = (MODE == 1) ? g_y1 : g_y2;
        #pragma unroll
        for (int mt = 0; mt < 4; mt++) {
            int r0 = m0 + wr * 64 + mt * 16 + qr;
            #pragma unroll
            for (int nt = 0; nt < 4; nt++) {
                int ncol = n0 + wc * 32 + nt * 8 + qc * 2;
                *(float2*)(Y + (size_t)r0 * ND + ncol) =
                    make_float2(acc[mt][nt][0], acc[mt][nt][1]);
                *(float2*)(Y + (size_t)(r0 + 8) * ND + ncol) =
                    make_float2(acc[mt][nt][2], acc[mt][nt][3]);
            }
        }
    }
}

// ================= proxy loss (b0 = batch-row offset) =======================
__global__ void __launch_bounds__(256) k_proxy_loss(const int* __restrict__ labels, int b0) {
    int b = b0 + blockIdx.x, tid = threadIdx.x;
    int lbl = labels[b];
    const float* row = g_cs + (size_t)b * NC;
    float lm = -3.4e38f;
    for (int i = tid; i < NC; i += 256) {
        float l = row[i];
        if (i == lbl) l -= MARGIN;
        lm = fmaxf(lm, l * INV_TEMP);
    }
    lm = block_reduce_max(lm);
    float se = 0.0f;
    for (int i = tid; i < NC; i += 256) {
        float l = row[i];
        if (i == lbl) l -= MARGIN;
        se += expf(l * INV_TEMP - lm);
    }
    se = block_reduce_sum(se);
    if (tid == 0) {
        float logit_lbl = (row[lbl] - MARGIN) * INV_TEMP;
        atomicAdd(&g_acc[0], (logf(se) + lm) - logit_lbl);
    }
}

// ================= enc LN + ReLU + proxy attention (bf16 P, smem-cached) ====
__global__ void __launch_bounds__(256) k_ln_att(const float* __restrict__ enc_b,
                                                const float* __restrict__ enc_g,
                                                const float* __restrict__ enc_beta,
                                                const int* __restrict__ labels) {
    int b = blockIdx.x, tid = threadIdx.x;
    __shared__ float e[ND];
    __shared__ float Ps[NP * ND];
    __shared__ float sdot[NP];
    const __nv_bfloat16* P = g_pB + (size_t)labels[b] * (NP * ND);
    #pragma unroll
    for (int r = 0; r < NP * 2; r++) {
        int i = tid + r * 256;
        __nv_bfloat162 p2 = *(const __nv_bfloat162*)(P + i * 2);
        Ps[i * 2]     = __bfloat162float(p2.x);
        Ps[i * 2 + 1] = __bfloat162float(p2.y);
    }

    float v[4], s = 0.0f, s2 = 0.0f;
    #pragma unroll
    for (int r = 0; r < 4; r++) {
        int i = tid + r * 256;
        float x = g_y1[(size_t)b * ND + i] + enc_b[i];
        v[r] = x; s += x; s2 += x * x;
    }
    s = block_reduce_sum(s);
    s2 = block_reduce_sum(s2);
    float mean = s * (1.0f / ND);
    float var = s2 * (1.0f / ND) - mean * mean;
    float rs = rsqrtf(var + 1e-5f);
    #pragma unroll
    for (int r = 0; r < 4; r++) {
        int i = tid + r * 256;
        e[i] = fmaxf((v[r] - mean) * rs * enc_g[i] + enc_beta[i], 0.0f);
    }
    __syncthreads();

    float part[NP];
    #pragma unroll
    for (int p = 0; p < NP; p++) part[p] = 0.0f;
    #pragma unroll
    for (int r = 0; r < 4; r++) {
        int i = tid + r * 256;
        float ev = e[i];
        #pragma unroll
        for (int p = 0; p < NP; p++) part[p] += Ps[p * ND + i] * ev;
    }
    #pragma unroll
    for (int p = 0; p < NP; p++) {
        float d = block_reduce_sum(part[p]);
        if (tid == 0) sdot[p] = d;
    }
    __syncthreads();

    float m = -3.4e38f;
    #pragma unroll
    for (int p = 0; p < NP; p++) m = fmaxf(m, sdot[p] * INV_TEMP);
    float w[NP], ws = 0.0f;
    #pragma unroll
    for (int p = 0; p < NP; p++) { w[p] = expf(sdot[p] * INV_TEMP - m); ws += w[p]; }
    float inv_ws = 1.0f / ws;
    #pragma unroll
    for (int r = 0; r < 4; r++) {
        int i = tid + r * 256;
        float c = 0.0f;
        #pragma unroll
        for (int p = 0; p < NP; p++) c += w[p] * Ps[p * ND + i];
        g_cA[(size_t)b * ND + i] = __float2bfloat16_rn(c * inv_ws);
    }
}

// ================= dec LN + masked recon loss (packed mask) =================
__global__ void __launch_bounds__(256) k_recon(const float* __restrict__ dec_b,
                                               const float* __restrict__ dec_g,
                                               const float* __restrict__ dec_beta,
                                               const float* __restrict__ features) {
    int b = blockIdx.x, tid = threadIdx.x;
    float v[4], s = 0.0f, s2 = 0.0f;
    #pragma unroll
    for (int r = 0; r < 4; r++) {
        int i = tid + r * 256;
        float x = g_y2[(size_t)b * ND + i] + dec_b[i];
        v[r] = x; s += x; s2 += x * x;
    }
    s = block_reduce_sum(s);
    s2 = block_reduce_sum(s2);
    float mean = s * (1.0f / ND);
    float var = s2 * (1.0f / ND) - mean * mean;
    float rs = rsqrtf(var + 1e-5f);
    float se = 0.0f;
    #pragma unroll
    for (int r = 0; r < 4; r++) {
        int i = tid + r * 256;
        size_t idx = (size_t)b * ND + i;
        unsigned mb = g_mbits[(size_t)b * (ND / 32) + (i >> 5)];
        float mask_inv = ((mb >> (i & 31)) & 1u) ? 0.0f : 1.0f;
        float recon = (v[r] - mean) * rs * dec_g[i] + dec_beta[i];
        float d = recon - features[idx];
        se += d * d * mask_inv;
    }
    se = block_reduce_sum(se);
    if (tid == 0) atomicAdd(&g_acc[1], se * (1.0f / (float)N_MASKED));
}

__global__ void k_final(float* __restrict__ out) {
    out[0] = (g_acc[0] + g_acc[1]) * (1.0f / (float)NB);
}

// ================= launch ===================================================
extern "C" void kernel_launch(void* const* d_in, const int* in_sizes, int n_in,
                              void* d_out, int out_size) {
    const float* features = (const float*)d_in[0];
    const float* proxies  = (const float*)d_in[1];
    const float* noise    = (const float*)d_in[2];
    const float* enc_w    = (const float*)d_in[3];
    const float* enc_b    = (const float*)d_in[4];
    const float* enc_g    = (const float*)d_in[5];
    const float* enc_beta = (const float*)d_in[6];
    const float* dec_w    = (const float*)d_in[7];
    const float* dec_b    = (const float*)d_in[8];
    const float* dec_g    = (const float*)d_in[9];
    const float* dec_beta = (const float*)d_in[10];
    const int*   labels   = (const int*)d_in[11];
    float* out = (float*)d_out;

    cudaFuncSetAttribute(k_gemm<0>, cudaFuncAttributeMaxDynamicSharedMemorySize, SMEM_GEMM);
    cudaFuncSetAttribute(k_gemm<1>, cudaFuncAttributeMaxDynamicSharedMemorySize, SMEM_GEMM);
    cudaFuncSetAttribute(k_gemm<2>, cudaFuncAttributeMaxDynamicSharedMemorySize, SMEM_GEMM);

    cudaStream_t s0 = 0;           // harness capture stream (legacy default)
    cudaStream_t s2;
    cudaStreamCreateWithFlags(&s2, cudaStreamNonBlocking);
    cudaEvent_t ev_fork, ev_fm, ev_nor, ev_g0a, ev_join;
    cudaEventCreateWithFlags(&ev_fork, cudaEventDisableTiming);
    cudaEventCreateWithFlags(&ev_fm,   cudaEventDisableTiming);
    cudaEventCreateWithFlags(&ev_nor,  cudaEventDisableTiming);
    cudaEventCreateWithFlags(&ev_g0a,  cudaEventDisableTiming);
    cudaEventCreateWithFlags(&ev_join, cudaEventDisableTiming);

    // fork s2 off the capture stream
    cudaEventRecord(ev_fork, s0);
    cudaStreamWaitEvent(s2, ev_fork, 0);

    // s2: featmask (g_fA, g_mA, g_mbits, g_acc init) then conv_w (weights)
    k_featmask<<<NB, 256, 0, s2>>>(features, noise);
    cudaEventRecord(ev_fm, s2);
    k_conv_w<<<(ND * ND / 4 + 255) / 256, 256, 0, s2>>>(enc_w, dec_w);

    // main: norm_prox (g_pB)
    k_norm_prox<<<NCP, 256, 0, s0>>>(proxies);
    cudaEventRecord(ev_nor, s0);

    // chain A on main: sim GEMM split over M halves -> proxy loss split
    cudaStreamWaitEvent(s0, ev_fm, 0);
    k_gemm<0><<<dim3(63, 16), 256, SMEM_GEMM, s0>>>(0);       // rows [0, 2048)
    cudaEventRecord(ev_g0a, s0);
    k_gemm<0><<<dim3(63, 16), 256, SMEM_GEMM, s0>>>(2048);    // rows [2048, 4096)
    k_proxy_loss<<<NB / 2, 256, 0, s0>>>(labels, 2048);       // second half

    // chain B on s2: enc GEMM -> ln_att (needs g_pB) -> dec GEMM -> recon
    k_gemm<1><<<dim3(8, 32), 256, SMEM_GEMM, s2>>>(0);
    cudaStreamWaitEvent(s2, ev_nor, 0);
    k_ln_att<<<NB, 256, 0, s2>>>(enc_b, enc_g, enc_beta, labels);
    k_gemm<2><<<dim3(8, 32), 256, SMEM_GEMM, s2>>>(0);
    k_recon<<<NB, 256, 0, s2>>>(dec_b, dec_g, dec_beta, features);
    // overlap first-half proxy loss with second-half sim GEMM
    cudaStreamWaitEvent(s2, ev_g0a, 0);
    k_proxy_loss<<<NB / 2, 256, 0, s2>>>(labels, 0);          // first half

    // join s2 back into the capture stream, then final reduce
    cudaEventRecord(ev_join, s2);
    cudaStreamWaitEvent(s0, ev_join, 0);
    k_final<<<1, 1, 0, s0>>>(out);

    cudaEventDestroy(ev_fork);
    cudaEventDestroy(ev_fm);
    cudaEventDestroy(ev_nor);
    cudaEventDestroy(ev_g0a);
    cudaEventDestroy(ev_join);
    cudaStreamDestroy(s2);
}